// round 13
// baseline (speedup 1.0000x reference)
#include <cuda_runtime.h>
#include <cstdint>

// CustomStrainEnergyLoss: mean over B of (trapz(y_pred - y_true, x, segments j < idx))^2
// integral_r = sum_{j=0}^{idx} w(j)*(p[j]-t[j]);
//   interior j<idx: w(j) = 0.5*(x[j+1]-x[max(j-1,0)])  (precomputed g_w)
//   j==idx:         w    = 0.5*(x[idx]-x[idx-1]) (idx>0), else 0
//
// ROUND 13: cp.async.bulk (UBLKCP) + mbarrier double-buffer pipeline.
// One elected thread per CTA keeps 2 stages x 12KB in flight -> ~192KB/SM
// outstanding, decoupling DRAM queue depth from warp scoreboard stalls
// (scalar-LDG structure was pinned at ~60% DRAM across 6 measured variants).

#define THREADS 256
#define MAX_N 8192
#define CHUNK 1024                 // elements per chunk (4KB per stream)
#define STAGES 2

__device__ float g_w[MAX_N];       // interior weights, valid for j < N-1

__global__ void prep_kernel(const float* __restrict__ x, float* out, int N) {
    int j = blockIdx.x * blockDim.x + threadIdx.x;
    if (j == 0) out[0] = 0.0f;
    if (j < N - 1) {
        float xm1 = x[j > 0 ? j - 1 : 0];
        g_w[j] = 0.5f * (x[j + 1] - xm1);
    }
}

__device__ __forceinline__ uint32_t smem_u32(const void* p) {
    return (uint32_t)__cvta_generic_to_shared(p);
}
__device__ __forceinline__ void mbar_init(uint32_t mbar, uint32_t count) {
    asm volatile("mbarrier.init.shared::cta.b64 [%0], %1;" :: "r"(mbar), "r"(count) : "memory");
}
__device__ __forceinline__ void mbar_expect_tx(uint32_t mbar, uint32_t bytes) {
    asm volatile("mbarrier.arrive.expect_tx.shared::cta.b64 _, [%0], %1;"
                 :: "r"(mbar), "r"(bytes) : "memory");
}
__device__ __forceinline__ void mbar_arrive(uint32_t mbar) {
    asm volatile("mbarrier.arrive.shared::cta.b64 _, [%0];" :: "r"(mbar) : "memory");
}
__device__ __forceinline__ void mbar_wait(uint32_t mbar, uint32_t parity) {
    asm volatile(
        "{\n\t"
        ".reg .pred P;\n\t"
        "WAIT_%=:\n\t"
        "mbarrier.try_wait.parity.acquire.cta.shared::cta.b64 P, [%0], %1, 0x989680;\n\t"
        "@P bra.uni DONE_%=;\n\t"
        "bra.uni WAIT_%=;\n\t"
        "DONE_%=:\n\t"
        "}" :: "r"(mbar), "r"(parity) : "memory");
}
__device__ __forceinline__ void bulk_cp(uint32_t dst_smem, const void* src, uint32_t bytes,
                                        uint32_t mbar) {
    asm volatile(
        "cp.async.bulk.shared::cta.global.mbarrier::complete_tx::bytes [%0], [%1], %2, [%3];"
        :: "r"(dst_smem), "l"(src), "r"(bytes), "r"(mbar) : "memory");
}

__global__ __launch_bounds__(THREADS, 8)
void strain_loss_kernel(const float* __restrict__ y_pred,
                        const float* __restrict__ y_true,
                        const float* __restrict__ x,
                        const int* __restrict__ fidx,
                        float* __restrict__ out,
                        int N, float inv_B) {
    __shared__ alignas(128) float sp[STAGES][CHUNK];
    __shared__ alignas(128) float st_[STAGES][CHUNK];
    __shared__ alignas(128) float sw[STAGES][CHUNK];
    __shared__ alignas(8) uint64_t bar_full[STAGES];
    __shared__ alignas(8) uint64_t bar_empty[STAGES];

    const int tid = threadIdx.x;
    const int r = blockIdx.x;

    int idx = fidx[r];
    idx = min(max(idx, 0), N - 1);
    const int n_el = idx + 1;
    const int nchunks = (n_el + CHUNK - 1) / CHUNK;

    if (tid == 0) {
        #pragma unroll
        for (int s = 0; s < STAGES; s++) {
            mbar_init(smem_u32(&bar_full[s]), 1);        // one expect_tx arriver
            mbar_init(smem_u32(&bar_empty[s]), THREADS); // all consumers arrive
        }
    }
    __syncthreads();

    const float* __restrict__ p = y_pred + (size_t)r * N;
    const float* __restrict__ t = y_true + (size_t)r * N;

    // exact weight for the boundary element j == idx (left term only)
    const float w_last = (idx > 0) ? 0.5f * (x[idx] - x[idx - 1]) : 0.0f;

    float acc = 0.0f;

    for (int c = 0; c < nchunks; c++) {
        const int s   = c & (STAGES - 1);
        const int phF = (c >> 1) & 1;        // consumer full-phase
        const int phE = phF ^ 1;             // producer empty-phase (starts 1: passes)
        const int start = c * CHUNK;
        const int len   = min(n_el - start, CHUNK);
        uint32_t rb = ((uint32_t)len * 4u + 15u) & ~15u;          // 16B-rounded
        const uint32_t maxb = (uint32_t)(N - start) * 4u;          // stay in row
        if (rb > maxb) rb = maxb;

        if (tid == 0) {
            mbar_wait(smem_u32(&bar_empty[s]), (uint32_t)phE);
            mbar_expect_tx(smem_u32(&bar_full[s]), 3u * rb);
            bulk_cp(smem_u32(&sp[s][0]),  p + start,   rb, smem_u32(&bar_full[s]));
            bulk_cp(smem_u32(&st_[s][0]), t + start,   rb, smem_u32(&bar_full[s]));
            bulk_cp(smem_u32(&sw[s][0]),  g_w + start, rb, smem_u32(&bar_full[s]));
        }

        mbar_wait(smem_u32(&bar_full[s]), (uint32_t)phF);

        // consume: each thread owns one float4 of the 1024-elem chunk
        {
            const int e = tid << 2;                    // element offset in chunk
            float4 a  = *(const float4*)&sp[s][e];
            float4 b  = *(const float4*)&st_[s][e];
            float4 cw = *(const float4*)&sw[s][e];
            const int j0 = start + e;
            #pragma unroll
            for (int k = 0; k < 4; k++) {
                const int j = j0 + k;
                float pv = (&a.x)[k], tv = (&b.x)[k], wv = (&cw.x)[k];
                if (j < idx)       acc = fmaf(wv,     pv - tv, acc);
                else if (j == idx) acc = fmaf(w_last, pv - tv, acc);
            }
        }

        mbar_arrive(smem_u32(&bar_empty[s]));
    }

    // Block reduction: warp shuffle then shared memory
    #pragma unroll
    for (int off = 16; off > 0; off >>= 1)
        acc += __shfl_xor_sync(0xFFFFFFFFu, acc, off);

    __shared__ float warp_sums[THREADS / 32];
    const int lane = tid & 31;
    const int wid  = tid >> 5;
    if (lane == 0) warp_sums[wid] = acc;
    __syncthreads();

    if (wid == 0) {
        float sum = (lane < THREADS / 32) ? warp_sums[lane] : 0.0f;
        #pragma unroll
        for (int off = 4; off > 0; off >>= 1)
            sum += __shfl_xor_sync(0xFFFFFFFFu, sum, off);
        if (lane == 0)
            atomicAdd(out, sum * sum * inv_B);   // err_sq pre-scaled by 1/B
    }
}

extern "C" void kernel_launch(void* const* d_in, const int* in_sizes, int n_in,
                              void* d_out, int out_size) {
    const float* y_pred = (const float*)d_in[0];
    const float* y_true = (const float*)d_in[1];
    const float* x_vals = (const float*)d_in[2];
    const int*   fidx   = (const int*)d_in[3];
    float* out = (float*)d_out;

    const int B = in_sizes[3];                                // fracture_idx count
    const int N = in_sizes[2] > MAX_N ? MAX_N : in_sizes[2];  // x_values count

    prep_kernel<<<(N + 255) / 256, 256>>>(x_vals, out, N);
    strain_loss_kernel<<<B, THREADS>>>(y_pred, y_true, x_vals, fidx, out,
                                       N, 1.0f / (float)B);
}

// round 14
// speedup vs baseline: 1.0045x; 1.0045x over previous
#include <cuda_runtime.h>

// CustomStrainEnergyLoss: mean over B of (trapz(y_pred - y_true, x, segments j < idx))^2
// integral_r = sum_{j=0}^{idx_r} w(j)*(p[j]-t[j]),
//   w(j) = 0.5*((j>0 ? x[j]-x[j-1] : 0) + (j<idx ? x[j+1]-x[j] : 0))
// Interior j (j < idx): w(j) = 0.5*(x[j+1]-x[max(j-1,0)])  (clamp -> j=0 exact).
// Weights are row-invariant: precomputed once into g_w (32KB, L2-resident).
//
// ROUND 14: deconflate R12. Keep the lean 3-LDG.128 loop (L1 busy 20% vs 53%)
// but force occupancy back to the proven-best level with __launch_bounds__
// (256, 8) -> regs capped at 32, 8 CTAs/SM (occ ~85%, where DRAM% peaked).
// p/t streams use __ldcs (evict-first): pure streaming, protect L2 for g_w/x.

#define THREADS 256
#define MAX_N 8192

__device__ float g_w[MAX_N];   // interior trapezoid weights, valid for j < N-1

__global__ void prep_kernel(const float* __restrict__ x, float* out, int N) {
    int j = blockIdx.x * blockDim.x + threadIdx.x;
    if (j == 0) out[0] = 0.0f;           // zero scalar output in same launch
    if (j < N - 1) {
        float xm1 = x[j > 0 ? j - 1 : 0];
        g_w[j] = 0.5f * (x[j + 1] - xm1);
    }
}

__global__ __launch_bounds__(THREADS, 8)
void strain_loss_kernel(const float* __restrict__ y_pred,
                        const float* __restrict__ y_true,
                        const float* __restrict__ x,
                        const int* __restrict__ fidx,
                        float* __restrict__ out,
                        int N, float inv_B) {
    const int r = blockIdx.x;
    int idx = fidx[r];
    idx = min(max(idx, 0), N - 1);
    const int nc = idx >> 2;   // clean interior float4 vectors: lanes j < idx

    const float* __restrict__ p = y_pred + (size_t)r * N;
    const float* __restrict__ t = y_true + (size_t)r * N;
    const float4* __restrict__ p4 = (const float4*)p;
    const float4* __restrict__ t4 = (const float4*)t;
    const float4* __restrict__ w4 = (const float4*)g_w;

    float acc = 0.0f;

    // Interior loop: 3 LDG.128 (p,t streaming evict-first; w L2-resident), 4 FMAs.
    for (int v = threadIdx.x; v < nc; v += THREADS) {
        float4 a = __ldcs(&p4[v]);
        float4 b = __ldcs(&t4[v]);
        float4 c = w4[v];
        acc = fmaf(c.x, a.x - b.x, acc);
        acc = fmaf(c.y, a.y - b.y, acc);
        acc = fmaf(c.z, a.z - b.z, acc);
        acc = fmaf(c.w, a.w - b.w, acc);
    }

    // Scalar tail: elements [4*nc, idx] (at most 4), exact trapezoid weights.
    for (int j = (nc << 2) + threadIdx.x; j <= idx; j += THREADS) {
        float left  = (j > 0)   ? (x[j] - x[j - 1]) : 0.0f;
        float right = (j < idx) ? (x[j + 1] - x[j]) : 0.0f;
        acc = fmaf(0.5f * (left + right), p[j] - t[j], acc);
    }

    // Block reduction: warp shuffle then shared memory (8 warps)
    #pragma unroll
    for (int off = 16; off > 0; off >>= 1)
        acc += __shfl_xor_sync(0xFFFFFFFFu, acc, off);

    __shared__ float warp_sums[THREADS / 32];
    const int lane = threadIdx.x & 31;
    const int wid  = threadIdx.x >> 5;
    if (lane == 0) warp_sums[wid] = acc;
    __syncthreads();

    if (wid == 0) {
        float s = (lane < THREADS / 32) ? warp_sums[lane] : 0.0f;
        #pragma unroll
        for (int off = 4; off > 0; off >>= 1)
            s += __shfl_xor_sync(0xFFFFFFFFu, s, off);
        if (lane == 0)
            atomicAdd(out, s * s * inv_B);   // err_sq pre-scaled by 1/B
    }
}

extern "C" void kernel_launch(void* const* d_in, const int* in_sizes, int n_in,
                              void* d_out, int out_size) {
    const float* y_pred = (const float*)d_in[0];
    const float* y_true = (const float*)d_in[1];
    const float* x_vals = (const float*)d_in[2];
    const int*   fidx   = (const int*)d_in[3];
    float* out = (float*)d_out;

    const int B = in_sizes[3];                                // fracture_idx count
    const int N = in_sizes[2] > MAX_N ? MAX_N : in_sizes[2];  // x_values count

    prep_kernel<<<(N + 255) / 256, 256>>>(x_vals, out, N);
    strain_loss_kernel<<<B, THREADS>>>(y_pred, y_true, x_vals, fidx, out,
                                       N, 1.0f / (float)B);
}

// round 16
// speedup vs baseline: 1.1907x; 1.1853x over previous
#include <cuda_runtime.h>
#include <cstdint>

// CustomStrainEnergyLoss: mean over B of (trapz(y_pred - y_true, x, segments j < idx))^2
// integral_r = sum_{j=0}^{idx_r} w(j)*(p[j]-t[j]),
//   w(j) = 0.5*((j>0 ? x[j]-x[j-1] : 0) + (j<idx ? x[j+1]-x[j] : 0))
// Interior j (j < idx): w(j) = 0.5*(x[j+1]-x[max(j-1,0)])  (clamp -> j=0 exact).
//
// ROUND 16 (rerun of untested R15; prior round was a container infra failure):
// cp.async(LDGSTS) 3-stage pipeline with PER-THREAD OWNED smem slots. Each
// thread async-copies and consumes only its own float4 -> no __syncthreads or
// mbarriers in the main loop; per-thread cp.async.wait_group is the only sync.
// Load issue is decoupled from warp scoreboards (LDGSTS lands in smem, no
// destination register) -> ~96B/thread (~190KB/SM) in flight, vs the ~60%-DRAM
// plateau of all eight measured synchronous-LDG variants.

#define THREADS 256
#define CHUNK_VEC 256     // float4 per chunk (1024 elements)
#define STAGES 3          // lookahead = 2 chunks

__global__ void zero_out_kernel(float* out) { out[0] = 0.0f; }

__device__ __forceinline__ void cp_async16(void* smem_dst, const void* gmem_src) {
    uint32_t d = (uint32_t)__cvta_generic_to_shared(smem_dst);
    asm volatile("cp.async.cg.shared.global [%0], [%1], 16;"
                 :: "r"(d), "l"(gmem_src) : "memory");
}
__device__ __forceinline__ void cp_commit() {
    asm volatile("cp.async.commit_group;" ::: "memory");
}
__device__ __forceinline__ void cp_wait_2() {
    asm volatile("cp.async.wait_group 2;" ::: "memory");
}
__device__ __forceinline__ void cp_wait_0() {
    asm volatile("cp.async.wait_group 0;" ::: "memory");
}

__global__ __launch_bounds__(THREADS)
void strain_loss_kernel(const float* __restrict__ y_pred,
                        const float* __restrict__ y_true,
                        const float* __restrict__ x,
                        const int* __restrict__ fidx,
                        float* __restrict__ out,
                        int N, float inv_B) {
    __shared__ alignas(16) float4 sp[STAGES][CHUNK_VEC];
    __shared__ alignas(16) float4 st[STAGES][CHUNK_VEC];
    __shared__ float warp_sums[THREADS / 32];

    const int tid = threadIdx.x;
    const int r = blockIdx.x;

    int idx = fidx[r];
    idx = min(max(idx, 0), N - 1);
    const int nc = idx >> 2;                                // clean interior vectors
    const int nchunks = (nc + CHUNK_VEC - 1) / CHUNK_VEC;

    const float* __restrict__ p = y_pred + (size_t)r * N;
    const float* __restrict__ t = y_true + (size_t)r * N;
    const float4* __restrict__ p4 = (const float4*)p;
    const float4* __restrict__ t4 = (const float4*)t;
    const float4* __restrict__ x4 = (const float4*)x;

    float acc = 0.0f;

    // prologue: fill the pipe with up to STAGES-1 chunks
    {
        const int pre = nchunks < (STAGES - 1) ? nchunks : (STAGES - 1);
        for (int i = 0; i < pre; i++) {
            const int v = i * CHUNK_VEC + tid;
            if (v < nc) {
                cp_async16(&sp[i][tid], &p4[v]);
                cp_async16(&st[i][tid], &t4[v]);
            }
            cp_commit();
        }
    }

    // body: issue chunk c+2, wait <=2 groups pending (chunk c complete), consume c
    int c = 0;
    for (; c + STAGES <= nchunks; c++) {
        {
            const int ci = c + STAGES - 1;
            const int v = ci * CHUNK_VEC + tid;
            const int s = ci % STAGES;
            if (v < nc) {
                cp_async16(&sp[s][tid], &p4[v]);
                cp_async16(&st[s][tid], &t4[v]);
            }
            cp_commit();
        }
        cp_wait_2();
        {
            const int v = c * CHUNK_VEC + tid;
            if (v < nc) {                       // always true in body, cheap guard
                const int s = c % STAGES;
                float4 a  = sp[s][tid];
                float4 b  = st[s][tid];
                const int j0 = v << 2;
                float4 xv = x4[v];
                float xm1 = x[j0 ? (j0 - 1) : 0];
                float xp4 = x[j0 + 4];          // j0+3 < idx <= N-1, safe
                acc = fmaf(0.5f * (xv.y - xm1),  a.x - b.x, acc);
                acc = fmaf(0.5f * (xv.z - xv.x), a.y - b.y, acc);
                acc = fmaf(0.5f * (xv.w - xv.y), a.z - b.z, acc);
                acc = fmaf(0.5f * (xp4  - xv.z), a.w - b.w, acc);
            }
        }
    }

    // drain: all chunks issued; wait for everything, consume the rest
    cp_wait_0();
    for (; c < nchunks; c++) {
        const int v = c * CHUNK_VEC + tid;
        if (v < nc) {
            const int s = c % STAGES;
            float4 a  = sp[s][tid];
            float4 b  = st[s][tid];
            const int j0 = v << 2;
            float4 xv = x4[v];
            float xm1 = x[j0 ? (j0 - 1) : 0];
            float xp4 = x[j0 + 4];
            acc = fmaf(0.5f * (xv.y - xm1),  a.x - b.x, acc);
            acc = fmaf(0.5f * (xv.z - xv.x), a.y - b.y, acc);
            acc = fmaf(0.5f * (xv.w - xv.y), a.z - b.z, acc);
            acc = fmaf(0.5f * (xp4  - xv.z), a.w - b.w, acc);
        }
    }

    // Scalar tail: elements [4*nc, idx] (at most 4), exact trapezoid weights.
    for (int j = (nc << 2) + tid; j <= idx; j += THREADS) {
        float left  = (j > 0)   ? (x[j] - x[j - 1]) : 0.0f;
        float right = (j < idx) ? (x[j + 1] - x[j]) : 0.0f;
        acc = fmaf(0.5f * (left + right), p[j] - t[j], acc);
    }

    // Block reduction: warp shuffle then shared memory (8 warps)
    #pragma unroll
    for (int off = 16; off > 0; off >>= 1)
        acc += __shfl_xor_sync(0xFFFFFFFFu, acc, off);

    const int lane = tid & 31;
    const int wid  = tid >> 5;
    if (lane == 0) warp_sums[wid] = acc;
    __syncthreads();

    if (wid == 0) {
        float s = (lane < THREADS / 32) ? warp_sums[lane] : 0.0f;
        #pragma unroll
        for (int off = 4; off > 0; off >>= 1)
            s += __shfl_xor_sync(0xFFFFFFFFu, s, off);
        if (lane == 0)
            atomicAdd(out, s * s * inv_B);   // err_sq pre-scaled by 1/B
    }
}

extern "C" void kernel_launch(void* const* d_in, const int* in_sizes, int n_in,
                              void* d_out, int out_size) {
    const float* y_pred = (const float*)d_in[0];
    const float* y_true = (const float*)d_in[1];
    const float* x_vals = (const float*)d_in[2];
    const int*   fidx   = (const int*)d_in[3];
    float* out = (float*)d_out;

    const int B = in_sizes[3];   // fracture_idx element count
    const int N = in_sizes[2];   // x_values element count

    zero_out_kernel<<<1, 1>>>(out);
    strain_loss_kernel<<<B, THREADS>>>(y_pred, y_true, x_vals, fidx, out,
                                       N, 1.0f / (float)B);
}

// round 17
// speedup vs baseline: 1.2011x; 1.0087x over previous
#include <cuda_runtime.h>
#include <cstdint>

// CustomStrainEnergyLoss: mean over B of (trapz(y_pred - y_true, x, segments j < idx))^2
// integral_r = sum_{j=0}^{idx_r} w(j)*(p[j]-t[j]),
//   w(j) = 0.5*((j>0 ? x[j]-x[j-1] : 0) + (j<idx ? x[j+1]-x[j] : 0))
// Interior j (j < idx): w(j) = 0.5*(x[j+1]-x[max(j-1,0)])  (clamp -> j=0 exact).
//
// ROUND 17: deepen the R16 cp.async pipeline (first structural win: 27.4us,
// DRAM 63.8%). STAGES 3->4: lookahead 3 chunks covers nearly the whole average
// row (~4.5 chunks) during the prologue, so the serial drain consumes data
// that is already resident instead of waiting. Body consume-guard removed
// (chunk c provably full when c+STAGES <= nchunks). Per-thread slot ownership,
// zero barriers/mbarriers in the main loop.

#define THREADS 256
#define CHUNK_VEC 256     // float4 per chunk (1024 elements)
#define STAGES 4          // lookahead = 3 chunks; smem = 4*2*4KB = 32KB

__global__ void zero_out_kernel(float* out) { out[0] = 0.0f; }

__device__ __forceinline__ void cp_async16(void* smem_dst, const void* gmem_src) {
    uint32_t d = (uint32_t)__cvta_generic_to_shared(smem_dst);
    asm volatile("cp.async.cg.shared.global [%0], [%1], 16;"
                 :: "r"(d), "l"(gmem_src) : "memory");
}
__device__ __forceinline__ void cp_commit() {
    asm volatile("cp.async.commit_group;" ::: "memory");
}
__device__ __forceinline__ void cp_wait_3() {
    asm volatile("cp.async.wait_group 3;" ::: "memory");
}
__device__ __forceinline__ void cp_wait_0() {
    asm volatile("cp.async.wait_group 0;" ::: "memory");
}

__global__ __launch_bounds__(THREADS)
void strain_loss_kernel(const float* __restrict__ y_pred,
                        const float* __restrict__ y_true,
                        const float* __restrict__ x,
                        const int* __restrict__ fidx,
                        float* __restrict__ out,
                        int N, float inv_B) {
    __shared__ alignas(16) float4 sp[STAGES][CHUNK_VEC];
    __shared__ alignas(16) float4 st[STAGES][CHUNK_VEC];
    __shared__ float warp_sums[THREADS / 32];

    const int tid = threadIdx.x;
    const int r = blockIdx.x;

    int idx = fidx[r];
    idx = min(max(idx, 0), N - 1);
    const int nc = idx >> 2;                                // clean interior vectors
    const int nchunks = (nc + CHUNK_VEC - 1) / CHUNK_VEC;

    const float* __restrict__ p = y_pred + (size_t)r * N;
    const float* __restrict__ t = y_true + (size_t)r * N;
    const float4* __restrict__ p4 = (const float4*)p;
    const float4* __restrict__ t4 = (const float4*)t;
    const float4* __restrict__ x4 = (const float4*)x;

    float acc = 0.0f;

    // prologue: fill the pipe with up to STAGES-1 chunks
    {
        const int pre = nchunks < (STAGES - 1) ? nchunks : (STAGES - 1);
        for (int i = 0; i < pre; i++) {
            const int v = i * CHUNK_VEC + tid;
            if (v < nc) {
                cp_async16(&sp[i][tid], &p4[v]);
                cp_async16(&st[i][tid], &t4[v]);
            }
            cp_commit();
        }
    }

    // body: issue chunk c+3, wait <=3 groups pending (chunk c complete), consume c.
    // For c <= nchunks-STAGES, chunk c is provably full -> no consume guard.
    int c = 0;
    for (; c + STAGES <= nchunks; c++) {
        {
            const int ci = c + STAGES - 1;
            const int v = ci * CHUNK_VEC + tid;
            const int s = ci & (STAGES - 1);
            if (v < nc) {
                cp_async16(&sp[s][tid], &p4[v]);
                cp_async16(&st[s][tid], &t4[v]);
            }
            cp_commit();
        }
        cp_wait_3();
        {
            const int v = c * CHUNK_VEC + tid;      // v < nc guaranteed
            const int s = c & (STAGES - 1);
            float4 a  = sp[s][tid];
            float4 b  = st[s][tid];
            const int j0 = v << 2;
            float4 xv = x4[v];
            float xm1 = x[j0 ? (j0 - 1) : 0];
            float xp4 = x[j0 + 4];                  // j0+3 < idx <= N-1, safe
            acc = fmaf(0.5f * (xv.y - xm1),  a.x - b.x, acc);
            acc = fmaf(0.5f * (xv.z - xv.x), a.y - b.y, acc);
            acc = fmaf(0.5f * (xv.w - xv.y), a.z - b.z, acc);
            acc = fmaf(0.5f * (xp4  - xv.z), a.w - b.w, acc);
        }
    }

    // drain: all chunks issued (data largely resident); wait, consume the rest
    cp_wait_0();
    for (; c < nchunks; c++) {
        const int v = c * CHUNK_VEC + tid;
        if (v < nc) {
            const int s = c & (STAGES - 1);
            float4 a  = sp[s][tid];
            float4 b  = st[s][tid];
            const int j0 = v << 2;
            float4 xv = x4[v];
            float xm1 = x[j0 ? (j0 - 1) : 0];
            float xp4 = x[j0 + 4];
            acc = fmaf(0.5f * (xv.y - xm1),  a.x - b.x, acc);
            acc = fmaf(0.5f * (xv.z - xv.x), a.y - b.y, acc);
            acc = fmaf(0.5f * (xv.w - xv.y), a.z - b.z, acc);
            acc = fmaf(0.5f * (xp4  - xv.z), a.w - b.w, acc);
        }
    }

    // Scalar tail: elements [4*nc, idx] (at most 4), exact trapezoid weights.
    for (int j = (nc << 2) + tid; j <= idx; j += THREADS) {
        float left  = (j > 0)   ? (x[j] - x[j - 1]) : 0.0f;
        float right = (j < idx) ? (x[j + 1] - x[j]) : 0.0f;
        acc = fmaf(0.5f * (left + right), p[j] - t[j], acc);
    }

    // Block reduction: warp shuffle then shared memory (8 warps)
    #pragma unroll
    for (int off = 16; off > 0; off >>= 1)
        acc += __shfl_xor_sync(0xFFFFFFFFu, acc, off);

    const int lane = tid & 31;
    const int wid  = tid >> 5;
    if (lane == 0) warp_sums[wid] = acc;
    __syncthreads();

    if (wid == 0) {
        float s = (lane < THREADS / 32) ? warp_sums[lane] : 0.0f;
        #pragma unroll
        for (int off = 4; off > 0; off >>= 1)
            s += __shfl_xor_sync(0xFFFFFFFFu, s, off);
        if (lane == 0)
            atomicAdd(out, s * s * inv_B);   // err_sq pre-scaled by 1/B
    }
}

extern "C" void kernel_launch(void* const* d_in, const int* in_sizes, int n_in,
                              void* d_out, int out_size) {
    const float* y_pred = (const float*)d_in[0];
    const float* y_true = (const float*)d_in[1];
    const float* x_vals = (const float*)d_in[2];
    const int*   fidx   = (const int*)d_in[3];
    float* out = (float*)d_out;

    const int B = in_sizes[3];   // fracture_idx element count
    const int N = in_sizes[2];   // x_values element count

    zero_out_kernel<<<1, 1>>>(out);
    strain_loss_kernel<<<B, THREADS>>>(y_pred, y_true, x_vals, fidx, out,
                                       N, 1.0f / (float)B);
}